// round 12
// baseline (speedup 1.0000x reference)
#include <cuda_runtime.h>
#include <cuda_bf16.h>
#include <cstdint>

// Problem constants
#define BATCH 512
#define SEQ 512
#define FD 128
#define RD 64
#define FW 768
#define KFLAT (FD*RD)   // 8192
#define KSPLIT 8
#define KCHUNK (KFLAT/KSPLIT)  // 1024
#define NUM_FILLERS 50257
#define NUM_ROLES 512

// Scratch (device globals)
__device__ __nv_bfloat16 g_f_hi[(size_t)NUM_FILLERS * FD];
__device__ __nv_bfloat16 g_f_lo[(size_t)NUM_FILLERS * FD];
__device__ __nv_bfloat16 g_r_hi[(size_t)NUM_ROLES * RD];
__device__ __nv_bfloat16 g_r_lo[(size_t)NUM_ROLES * RD];
__device__ __nv_bfloat16 g_a_hi[(size_t)BATCH * KFLAT];
__device__ __nv_bfloat16 g_a_lo[(size_t)BATCH * KFLAT];
__device__ __nv_bfloat16 g_w_hi[(size_t)FW * KFLAT];
__device__ __nv_bfloat16 g_w_lo[(size_t)FW * KFLAT];
__device__ float g_partial[(size_t)KSPLIT * BATCH * FW];
__device__ int   g_flags[2];

__device__ __forceinline__ uint32_t smem_u32(const void* p) {
    uint32_t a;
    asm("{ .reg .u64 t; cvta.to.shared.u64 t, %1; cvt.u32.u64 %0, t; }" : "=r"(a) : "l"(p));
    return a;
}

// ---- cp.async helpers -----------------------------------------------------
#define CP_ASYNC16(dst, src) \
    asm volatile("cp.async.cg.shared.global [%0], [%1], 16;" :: "r"(dst), "l"(src))
#define CP_COMMIT() asm volatile("cp.async.commit_group;" ::: "memory")
#define CP_WAIT(N)  asm volatile("cp.async.wait_group %0;" :: "n"(N) : "memory")

// ---- warp mma helpers -----------------------------------------------------
#define LDSM4(r, addr) \
    asm volatile("ldmatrix.sync.aligned.m8n8.x4.shared.b16 {%0,%1,%2,%3}, [%4];" \
        : "=r"((r)[0]), "=r"((r)[1]), "=r"((r)[2]), "=r"((r)[3]) : "r"(addr))

#define LDSM4T(r, addr) \
    asm volatile("ldmatrix.sync.aligned.m8n8.x4.trans.shared.b16 {%0,%1,%2,%3}, [%4];" \
        : "=r"((r)[0]), "=r"((r)[1]), "=r"((r)[2]), "=r"((r)[3]) : "r"(addr))

#define MMA16816(d, a, b0, b1) \
    asm volatile("mma.sync.aligned.m16n8k16.row.col.f32.bf16.bf16.f32 " \
        "{%0,%1,%2,%3}, {%4,%5,%6,%7}, {%8,%9}, {%0,%1,%2,%3};" \
        : "+f"((d)[0]), "+f"((d)[1]), "+f"((d)[2]), "+f"((d)[3]) \
        : "r"((a)[0]), "r"((a)[1]), "r"((a)[2]), "r"((a)[3]), "r"(b0), "r"(b1))

__device__ __forceinline__ void bf16_split4(float4 v, uint2& h, uint2& l) {
    __nv_bfloat16 h0 = __float2bfloat16(v.x), h1 = __float2bfloat16(v.y);
    __nv_bfloat16 h2 = __float2bfloat16(v.z), h3 = __float2bfloat16(v.w);
    __nv_bfloat162 hp0{h0, h1}, hp1{h2, h3};
    __nv_bfloat162 lp0{__float2bfloat16(v.x - __bfloat162float(h0)),
                       __float2bfloat16(v.y - __bfloat162float(h1))};
    __nv_bfloat162 lp1{__float2bfloat16(v.z - __bfloat162float(h2)),
                       __float2bfloat16(v.w - __bfloat162float(h3))};
    h.x = *(unsigned*)&hp0; h.y = *(unsigned*)&hp1;
    l.x = *(unsigned*)&lp0; l.y = *(unsigned*)&lp1;
}
__device__ __forceinline__ void bf16_split2(float a, float b, unsigned& h, unsigned& l) {
    __nv_bfloat16 h0 = __float2bfloat16(a), h1 = __float2bfloat16(b);
    __nv_bfloat162 hp{h0, h1};
    __nv_bfloat162 lp{__float2bfloat16(a - __bfloat162float(h0)),
                      __float2bfloat16(b - __bfloat162float(h1))};
    h = *(unsigned*)&hp; l = *(unsigned*)&lp;
}

// ---------------------------------------------------------------------------
// Kernel 0: input disambiguation
// ---------------------------------------------------------------------------
__global__ void detect_kernel(const int* __restrict__ a, const int* __restrict__ b)
{
    if (threadIdx.x != 0 || blockIdx.x != 0) return;
    int odd = 0;
#pragma unroll 8
    for (int i = 0; i < 256; i++) odd |= a[2 * i + 1];
    const int is64 = (odd == 0) ? 1 : 0;
    const int s = is64 ? 2 : 1;
    int amax = 0, bmax = 0;
#pragma unroll 8
    for (int i = 0; i < 256; i++) {
        amax = max(amax, a[i * s]);
        bmax = max(bmax, b[i * s]);
    }
    g_flags[0] = (amax < NUM_ROLES && bmax >= NUM_ROLES) ? 1 : 0;
    g_flags[1] = is64;
}

// ---------------------------------------------------------------------------
// One-shot fp32 -> bf16 hi/lo converter (W + filler table + role table fused)
// ---------------------------------------------------------------------------
#define W4   ((size_t)FW * KFLAT / 4)
#define F4   ((size_t)NUM_FILLERS * FD / 4)
#define R4   ((size_t)NUM_ROLES * RD / 4)
#define W_BLK  6144
#define F_BLK  6283
#define R_BLK  32
__global__ __launch_bounds__(256) void convert_all(
    const float* __restrict__ W, const float* __restrict__ FT,
    const float* __restrict__ RT)
{
    const int bx = blockIdx.x;
    const float* src;
    __nv_bfloat16 *dh, *dl;
    size_t i, n;
    if (bx < W_BLK) {
        i = (size_t)bx * 256 + threadIdx.x; n = W4;
        src = W; dh = g_w_hi; dl = g_w_lo;
    } else if (bx < W_BLK + F_BLK) {
        i = (size_t)(bx - W_BLK) * 256 + threadIdx.x; n = F4;
        src = FT; dh = g_f_hi; dl = g_f_lo;
    } else {
        i = (size_t)(bx - W_BLK - F_BLK) * 256 + threadIdx.x; n = R4;
        src = RT; dh = g_r_hi; dl = g_r_lo;
    }
    if (i >= n) return;
    float4 v = ((const float4*)src)[i];
    uint2 h, l;
    bf16_split4(v, h, l);
    ((uint2*)dh)[i] = h;
    ((uint2*)dl)[i] = l;
}

// ---------------------------------------------------------------------------
// Kernel 1: tensorized outer products, 3-stage cp.async, 1 sync per iter.
//   outer[b] = fe^T @ re : M=128 x N=64 x K=512, bf16 3-pass, fp32 accum.
// grid = 512, 128 threads (4 warps, M split 4x32), warp tile 32(M) x 64(N).
// ---------------------------------------------------------------------------
#define FE_PITCHB 272
#define RE_PITCHB 144
#define O_FEH 0
#define O_FEL 8704
#define O_REH 17408
#define O_REL 22016
#define O_STAGE 26624
#define O_STAGES 3
#define OUTER_DYN (O_STAGES * O_STAGE)
#define O_NT (SEQ / 32)   // 16

__global__ __launch_bounds__(128) void outer_tc(
    const int* __restrict__ ia, const int* __restrict__ ib)
{
    extern __shared__ char dsm[];
    __shared__ int sf[SEQ], sr[SEQ];

    const int b    = blockIdx.x;
    const int tid  = threadIdx.x;
    const int lane = tid & 31;
    const int wid  = tid >> 5;      // 0..3
    const int wm   = wid * 32;

    const int swap = g_flags[0];
    const int strd = g_flags[1] ? 2 : 1;
    const int* __restrict__ fidx = swap ? ib : ia;
    const int* __restrict__ ridx = swap ? ia : ib;

    for (int i = tid; i < SEQ; i += 128) {
        size_t e = (size_t)b * SEQ + i;
        sf[i] = min(max(fidx[e * strd], 0), NUM_FILLERS - 1);
        sr[i] = min(max(ridx[e * strd], 0), NUM_ROLES - 1);
    }
    __syncthreads();

    const uint32_t smb = smem_u32(dsm);

    const int fr = tid >> 4, fc = tid & 15;
    const int rr = tid >> 3, rc = tid & 7;

    // Guarded issue: loads only if kt valid; commit ALWAYS (keeps group count).
    auto issue_tile = [&](int kt) {
        if (kt < O_NT) {
            const int k0 = kt * 32;
            const uint32_t base = smb + (kt % O_STAGES) * O_STAGE;
#pragma unroll
            for (int u = 0; u < 4; u++) {
                int row = fr + u * 8;
                uint32_t d = base + row * FE_PITCHB + fc * 16;
                size_t s = (size_t)sf[k0 + row] * FD + fc * 8;
                CP_ASYNC16(d + O_FEH, g_f_hi + s);
                CP_ASYNC16(d + O_FEL, g_f_lo + s);
            }
#pragma unroll
            for (int u = 0; u < 2; u++) {
                int row = rr + u * 16;
                uint32_t d = base + row * RE_PITCHB + rc * 16;
                size_t s = (size_t)sr[k0 + row] * RD + rc * 8;
                CP_ASYNC16(d + O_REH, g_r_hi + s);
                CP_ASYNC16(d + O_REL, g_r_lo + s);
            }
        }
        CP_COMMIT();
    };

    const uint32_t aoff = (uint32_t)((lane & 7) + ((lane >> 4) & 1) * 8) * FE_PITCHB
                        + (uint32_t)(wm + ((lane >> 3) & 1) * 8) * 2;
    const uint32_t boff = (uint32_t)((lane & 7) + ((lane >> 3) & 1) * 8) * RE_PITCHB
                        + (uint32_t)(((lane >> 4) & 1) * 8) * 2;

    float acc[2][8][4];
#pragma unroll
    for (int i = 0; i < 2; i++)
#pragma unroll
        for (int j = 0; j < 8; j++)
#pragma unroll
            for (int q = 0; q < 4; q++) acc[i][j][q] = 0.f;

    issue_tile(0);
    issue_tile(1);

    for (int kt = 0; kt < O_NT; kt++) {
        CP_WAIT(1);              // tile kt resident
        __syncthreads();         // all warps done with buf (kt-1)%3 == (kt+2)%3
        issue_tile(kt + 2);      // prefetch into (kt+2)%3

        const uint32_t base = smb + (kt % O_STAGES) * O_STAGE;
#pragma unroll
        for (int s = 0; s < 2; s++) {
            const uint32_t arow  = base + O_FEH + aoff + (uint32_t)(s * 16) * FE_PITCHB;
            const uint32_t alrow = arow + (O_FEL - O_FEH);
            const uint32_t brow  = base + O_REH + boff + (uint32_t)(s * 16) * RE_PITCHB;
            const uint32_t blrow = brow + (O_REL - O_REH);
            uint32_t ah[2][4], al[2][4];
#pragma unroll
            for (int mi = 0; mi < 2; mi++) {
                LDSM4T(ah[mi], arow + mi * 32);
                LDSM4T(al[mi], alrow + mi * 32);
            }
            uint32_t bh[4][4], bl[4][4];
#pragma unroll
            for (int n16 = 0; n16 < 4; n16++) {
                LDSM4T(bh[n16], brow + n16 * 32);
                LDSM4T(bl[n16], blrow + n16 * 32);
            }
#pragma unroll
            for (int mi = 0; mi < 2; mi++)
#pragma unroll
                for (int n16 = 0; n16 < 4; n16++)
#pragma unroll
                    for (int h = 0; h < 2; h++) {
                        float* d = acc[mi][n16 * 2 + h];
                        MMA16816(d, ah[mi], bh[n16][h * 2], bh[n16][h * 2 + 1]);
                        MMA16816(d, ah[mi], bl[n16][h * 2], bl[n16][h * 2 + 1]);
                        MMA16816(d, al[mi], bh[n16][h * 2], bh[n16][h * 2 + 1]);
                    }
        }
    }

    const int rrow = lane >> 2, rcol = (lane & 3) * 2;
#pragma unroll
    for (int mi = 0; mi < 2; mi++)
#pragma unroll
        for (int nj = 0; nj < 8; nj++) {
            float* d = acc[mi][nj];
            int m = wm + mi * 16 + rrow;
            int n = nj * 8 + rcol;
            size_t off = (size_t)b * KFLAT + (size_t)m * RD + n;
            unsigned h, l;
            bf16_split2(d[0], d[1], h, l);
            *(unsigned*)(g_a_hi + off) = h;
            *(unsigned*)(g_a_lo + off) = l;
            bf16_split2(d[2], d[3], h, l);
            *(unsigned*)(g_a_hi + off + 8 * RD) = h;
            *(unsigned*)(g_a_lo + off + 8 * RD) = l;
        }
}

// ---------------------------------------------------------------------------
// Kernel 2: warp-mma split-K GEMM, 3-stage cp.async, 1 sync per iter.
// grid = (4, 12, KSPLIT), 128 threads (4 warps, M split 4x32),
// warp tile 32(M) x 64(N), CTA 128x64, K-tile 32.
// ---------------------------------------------------------------------------
#define PITCHB 80
#define G_AH 0
#define G_AL 10240
#define G_BH 20480
#define G_BL 25600
#define G_STAGE 30720
#define G_STAGES 3
#define GEMM2_DYN (G_STAGES * G_STAGE)
#define G_NT (KCHUNK / 32)   // 32

__global__ __launch_bounds__(128) void gemm2_mma()
{
    extern __shared__ char dsm[];
    const int tid  = threadIdx.x;
    const int lane = tid & 31;
    const int wid  = tid >> 5;
    const int wm   = wid * 32;

    const int mtile = blockIdx.x, ntile = blockIdx.y, ks = blockIdx.z;
    const size_t arow0 = (size_t)(mtile * 128) * KFLAT;
    const size_t brow0 = (size_t)(ntile * 64) * KFLAT;
    const int kbase = ks * KCHUNK;

    const uint32_t smb = smem_u32(dsm);
    const int row = tid >> 2, c = tid & 3;

    auto issue_tile = [&](int it) {
        if (it < G_NT) {
            const int kg = kbase + it * 32;
            const uint32_t base = smb + (it % G_STAGES) * G_STAGE;
#pragma unroll
            for (int u = 0; u < 4; u++) {
                int r2 = row + u * 32;
                uint32_t d = base + r2 * PITCHB + c * 16;
                size_t s = arow0 + (size_t)r2 * KFLAT + kg + c * 8;
                CP_ASYNC16(d + G_AH, g_a_hi + s);
                CP_ASYNC16(d + G_AL, g_a_lo + s);
            }
#pragma unroll
            for (int u = 0; u < 2; u++) {
                int r2 = row + u * 32;
                uint32_t d = base + r2 * PITCHB + c * 16;
                size_t s = brow0 + (size_t)r2 * KFLAT + kg + c * 8;
                CP_ASYNC16(d + G_BH, g_w_hi + s);
                CP_ASYNC16(d + G_BL, g_w_lo + s);
            }
        }
        CP_COMMIT();
    };

    const uint32_t a_off0 = (uint32_t)(wm + (lane & 15)) * PITCHB + ((lane >> 4) << 4);
    const uint32_t b_off0 = (uint32_t)(((lane >> 4) << 3) + (lane & 7)) * PITCHB
                          + (((lane >> 3) & 1) << 4);

    float acc[2][8][4];
#pragma unroll
    for (int i = 0; i < 2; i++)
#pragma unroll
        for (int j = 0; j < 8; j++)
#pragma unroll
            for (int q = 0; q < 4; q++) acc[i][j][q] = 0.f;

    issue_tile(0);
    issue_tile(1);

    for (int it = 0; it < G_NT; it++) {
        CP_WAIT(1);
        __syncthreads();
        issue_tile(it + 2);

        const uint32_t base = smb + (it % G_STAGES) * G_STAGE;
#pragma unroll
        for (int s = 0; s < 2; s++) {
            const uint32_t koff = s * 32;
            uint32_t ah[2][4], al[2][4];
#pragma unroll
            for (int i = 0; i < 2; i++) {
                uint32_t off = a_off0 + (uint32_t)(i * 16) * PITCHB + koff;
                LDSM4(ah[i], base + G_AH + off);
                LDSM4(al[i], base + G_AL + off);
            }
            uint32_t bh[4][4], bl[4][4];
#pragma unroll
            for (int j = 0; j < 4; j++) {
                uint32_t off = b_off0 + (uint32_t)(j * 16) * PITCHB + koff;
                LDSM4(bh[j], base + G_BH + off);
                LDSM4(bl[j], base + G_BL + off);
            }
#pragma unroll
            for (int i = 0; i < 2; i++)
#pragma unroll
                for (int j = 0; j < 4; j++)
#pragma unroll
                    for (int h = 0; h < 2; h++) {
                        float* d = acc[i][j * 2 + h];
                        MMA16816(d, ah[i], bh[j][h * 2], bh[j][h * 2 + 1]);
                        MMA16816(d, ah[i], bl[j][h * 2], bl[j][h * 2 + 1]);
                        MMA16816(d, al[i], bh[j][h * 2], bh[j][h * 2 + 1]);
                    }
        }
    }

    const int rbase = mtile * 128 + wm + (lane >> 2);
    const int cbase = ntile * 64 + (lane & 3) * 2;
    float* P = g_partial + (size_t)ks * BATCH * FW;
#pragma unroll
    for (int i = 0; i < 2; i++)
#pragma unroll
        for (int nj = 0; nj < 8; nj++) {
            float* d = acc[i][nj];
            size_t r0 = (size_t)(rbase + i * 16) * FW + cbase + nj * 8;
            *(float2*)&P[r0]          = make_float2(d[0], d[1]);
            *(float2*)&P[r0 + 8 * FW] = make_float2(d[2], d[3]);
        }
}

// ---------------------------------------------------------------------------
// Kernel 3: reduce split-K partials + bias -> out[1][B][FW]
// ---------------------------------------------------------------------------
__global__ void reduce_kernel(const float* __restrict__ bias, float* __restrict__ out)
{
    int idx = blockIdx.x * 256 + threadIdx.x;
    if (idx < BATCH * FW) {
        int n = idx % FW;
        float s = bias[n];
#pragma unroll
        for (int ks = 0; ks < KSPLIT; ks++)
            s += g_partial[(size_t)ks * BATCH * FW + idx];
        out[idx] = s;
    }
}

// ---------------------------------------------------------------------------
extern "C" void kernel_launch(void* const* d_in, const int* in_sizes, int n_in,
                              void* d_out, int out_size)
{
    const void* idx_arr[2] = {nullptr, nullptr};
    int n_idx = 0;
    const float* ftab = nullptr;
    const float* rtab = nullptr;
    const float* W    = nullptr;
    const float* bias = nullptr;

    for (int i = 0; i < n_in; i++) {
        switch (in_sizes[i]) {
            case BATCH * SEQ:
                if (n_idx < 2) idx_arr[n_idx++] = d_in[i];
                break;
            case NUM_FILLERS * FD: ftab = (const float*)d_in[i]; break;
            case NUM_ROLES * RD:   rtab = (const float*)d_in[i]; break;
            case FW * KFLAT:       W    = (const float*)d_in[i]; break;
            case FW:               bias = (const float*)d_in[i]; break;
            default: break;
        }
    }

    const int* ia = (const int*)idx_arr[0];
    const int* ib = (const int*)idx_arr[1];
    float* out = (float*)d_out;

    static bool attr_done = false;
    if (!attr_done) {
        cudaFuncSetAttribute(outer_tc, cudaFuncAttributeMaxDynamicSharedMemorySize, OUTER_DYN);
        cudaFuncSetAttribute(gemm2_mma, cudaFuncAttributeMaxDynamicSharedMemorySize, GEMM2_DYN);
        attr_done = true;
    }

    detect_kernel<<<1, 1>>>(ia, ib);
    convert_all<<<W_BLK + F_BLK + R_BLK, 256>>>(W, ftab, rtab);

    outer_tc<<<BATCH, 128, OUTER_DYN>>>(ia, ib);

    dim3 grid2(BATCH / 128, FW / 64, KSPLIT);
    gemm2_mma<<<grid2, 128, GEMM2_DYN>>>();

    reduce_kernel<<<(BATCH * FW + 255) / 256, 256>>>(bias, out);
}

// round 13
// speedup vs baseline: 1.0577x; 1.0577x over previous
#include <cuda_runtime.h>
#include <cuda_bf16.h>
#include <cstdint>

// Problem constants
#define BATCH 512
#define SEQ 512
#define FD 128
#define RD 64
#define FW 768
#define KFLAT (FD*RD)   // 8192
#define KSPLIT 16
#define KCHUNK (KFLAT/KSPLIT)  // 512
#define NUM_FILLERS 50257
#define NUM_ROLES 512

// Scratch (device globals)
__device__ __nv_bfloat16 g_f_hi[(size_t)NUM_FILLERS * FD];
__device__ __nv_bfloat16 g_f_lo[(size_t)NUM_FILLERS * FD];
__device__ __nv_bfloat16 g_r_hi[(size_t)NUM_ROLES * RD];
__device__ __nv_bfloat16 g_r_lo[(size_t)NUM_ROLES * RD];
__device__ __nv_bfloat16 g_a_hi[(size_t)BATCH * KFLAT];
__device__ __nv_bfloat16 g_a_lo[(size_t)BATCH * KFLAT];
__device__ __nv_bfloat16 g_w_hi[(size_t)FW * KFLAT];
__device__ __nv_bfloat16 g_w_lo[(size_t)FW * KFLAT];
__device__ float g_partial[(size_t)KSPLIT * BATCH * FW];   // 25.2 MB
__device__ int   g_flags[2];

__device__ __forceinline__ uint32_t smem_u32(const void* p) {
    uint32_t a;
    asm("{ .reg .u64 t; cvta.to.shared.u64 t, %1; cvt.u32.u64 %0, t; }" : "=r"(a) : "l"(p));
    return a;
}

// ---- cp.async helpers -----------------------------------------------------
#define CP_ASYNC16(dst, src) \
    asm volatile("cp.async.cg.shared.global [%0], [%1], 16;" :: "r"(dst), "l"(src))
#define CP_COMMIT() asm volatile("cp.async.commit_group;" ::: "memory")
#define CP_WAIT(N)  asm volatile("cp.async.wait_group %0;" :: "n"(N) : "memory")

// ---- warp mma helpers -----------------------------------------------------
#define LDSM4(r, addr) \
    asm volatile("ldmatrix.sync.aligned.m8n8.x4.shared.b16 {%0,%1,%2,%3}, [%4];" \
        : "=r"((r)[0]), "=r"((r)[1]), "=r"((r)[2]), "=r"((r)[3]) : "r"(addr))

#define LDSM4T(r, addr) \
    asm volatile("ldmatrix.sync.aligned.m8n8.x4.trans.shared.b16 {%0,%1,%2,%3}, [%4];" \
        : "=r"((r)[0]), "=r"((r)[1]), "=r"((r)[2]), "=r"((r)[3]) : "r"(addr))

#define MMA16816(d, a, b0, b1) \
    asm volatile("mma.sync.aligned.m16n8k16.row.col.f32.bf16.bf16.f32 " \
        "{%0,%1,%2,%3}, {%4,%5,%6,%7}, {%8,%9}, {%0,%1,%2,%3};" \
        : "+f"((d)[0]), "+f"((d)[1]), "+f"((d)[2]), "+f"((d)[3]) \
        : "r"((a)[0]), "r"((a)[1]), "r"((a)[2]), "r"((a)[3]), "r"(b0), "r"(b1))

__device__ __forceinline__ void bf16_split4(float4 v, uint2& h, uint2& l) {
    __nv_bfloat16 h0 = __float2bfloat16(v.x), h1 = __float2bfloat16(v.y);
    __nv_bfloat16 h2 = __float2bfloat16(v.z), h3 = __float2bfloat16(v.w);
    __nv_bfloat162 hp0{h0, h1}, hp1{h2, h3};
    __nv_bfloat162 lp0{__float2bfloat16(v.x - __bfloat162float(h0)),
                       __float2bfloat16(v.y - __bfloat162float(h1))};
    __nv_bfloat162 lp1{__float2bfloat16(v.z - __bfloat162float(h2)),
                       __float2bfloat16(v.w - __bfloat162float(h3))};
    h.x = *(unsigned*)&hp0; h.y = *(unsigned*)&hp1;
    l.x = *(unsigned*)&lp0; l.y = *(unsigned*)&lp1;
}
__device__ __forceinline__ void bf16_split2(float a, float b, unsigned& h, unsigned& l) {
    __nv_bfloat16 h0 = __float2bfloat16(a), h1 = __float2bfloat16(b);
    __nv_bfloat162 hp{h0, h1};
    __nv_bfloat162 lp{__float2bfloat16(a - __bfloat162float(h0)),
                      __float2bfloat16(b - __bfloat162float(h1))};
    h = *(unsigned*)&hp; l = *(unsigned*)&lp;
}

// ---------------------------------------------------------------------------
// Kernel 0: input disambiguation
// ---------------------------------------------------------------------------
__global__ void detect_kernel(const int* __restrict__ a, const int* __restrict__ b)
{
    if (threadIdx.x != 0 || blockIdx.x != 0) return;
    int odd = 0;
#pragma unroll 8
    for (int i = 0; i < 256; i++) odd |= a[2 * i + 1];
    const int is64 = (odd == 0) ? 1 : 0;
    const int s = is64 ? 2 : 1;
    int amax = 0, bmax = 0;
#pragma unroll 8
    for (int i = 0; i < 256; i++) {
        amax = max(amax, a[i * s]);
        bmax = max(bmax, b[i * s]);
    }
    g_flags[0] = (amax < NUM_ROLES && bmax >= NUM_ROLES) ? 1 : 0;
    g_flags[1] = is64;
}

// ---------------------------------------------------------------------------
// One-shot fp32 -> bf16 hi/lo converter (W + filler table + role table fused)
// ---------------------------------------------------------------------------
#define W4   ((size_t)FW * KFLAT / 4)
#define F4   ((size_t)NUM_FILLERS * FD / 4)
#define R4   ((size_t)NUM_ROLES * RD / 4)
#define W_BLK  6144
#define F_BLK  6283
#define R_BLK  32
__global__ __launch_bounds__(256) void convert_all(
    const float* __restrict__ W, const float* __restrict__ FT,
    const float* __restrict__ RT)
{
    const int bx = blockIdx.x;
    const float* src;
    __nv_bfloat16 *dh, *dl;
    size_t i, n;
    if (bx < W_BLK) {
        i = (size_t)bx * 256 + threadIdx.x; n = W4;
        src = W; dh = g_w_hi; dl = g_w_lo;
    } else if (bx < W_BLK + F_BLK) {
        i = (size_t)(bx - W_BLK) * 256 + threadIdx.x; n = F4;
        src = FT; dh = g_f_hi; dl = g_f_lo;
    } else {
        i = (size_t)(bx - W_BLK - F_BLK) * 256 + threadIdx.x; n = R4;
        src = RT; dh = g_r_hi; dl = g_r_lo;
    }
    if (i >= n) return;
    float4 v = ((const float4*)src)[i];
    uint2 h, l;
    bf16_split4(v, h, l);
    ((uint2*)dh)[i] = h;
    ((uint2*)dl)[i] = l;
}

// ---------------------------------------------------------------------------
// Kernel 1: tensorized outer products, cp.async double-buffered (R11 config).
//   outer[b] = fe^T @ re : M=128 x N=64 x K=512, bf16 3-pass, fp32 accum.
// grid = 512, 128 threads (4 warps, M split 4x32), warp tile 32(M) x 64(N).
// ---------------------------------------------------------------------------
#define FE_PITCHB 272
#define RE_PITCHB 144
#define O_FEH 0
#define O_FEL 8704
#define O_REH 17408
#define O_REL 22016
#define O_STAGE 26624
#define OUTER_DYN (2 * O_STAGE)
#define O_NT (SEQ / 32)   // 16

__global__ __launch_bounds__(128) void outer_tc(
    const int* __restrict__ ia, const int* __restrict__ ib)
{
    extern __shared__ char dsm[];
    __shared__ int sf[SEQ], sr[SEQ];

    const int b    = blockIdx.x;
    const int tid  = threadIdx.x;
    const int lane = tid & 31;
    const int wid  = tid >> 5;      // 0..3
    const int wm   = wid * 32;

    const int swap = g_flags[0];
    const int strd = g_flags[1] ? 2 : 1;
    const int* __restrict__ fidx = swap ? ib : ia;
    const int* __restrict__ ridx = swap ? ia : ib;

    for (int i = tid; i < SEQ; i += 128) {
        size_t e = (size_t)b * SEQ + i;
        sf[i] = min(max(fidx[e * strd], 0), NUM_FILLERS - 1);
        sr[i] = min(max(ridx[e * strd], 0), NUM_ROLES - 1);
    }
    __syncthreads();

    const uint32_t smb = smem_u32(dsm);

    const int fr = tid >> 4, fc = tid & 15;
    const int rr = tid >> 3, rc = tid & 7;

    auto issue_tile = [&](int kt, int st) {
        const int k0 = kt * 32;
        const uint32_t base = smb + st * O_STAGE;
#pragma unroll
        for (int u = 0; u < 4; u++) {
            int row = fr + u * 8;
            uint32_t d = base + row * FE_PITCHB + fc * 16;
            size_t s = (size_t)sf[k0 + row] * FD + fc * 8;
            CP_ASYNC16(d + O_FEH, g_f_hi + s);
            CP_ASYNC16(d + O_FEL, g_f_lo + s);
        }
#pragma unroll
        for (int u = 0; u < 2; u++) {
            int row = rr + u * 16;
            uint32_t d = base + row * RE_PITCHB + rc * 16;
            size_t s = (size_t)sr[k0 + row] * RD + rc * 8;
            CP_ASYNC16(d + O_REH, g_r_hi + s);
            CP_ASYNC16(d + O_REL, g_r_lo + s);
        }
        CP_COMMIT();
    };

    const uint32_t aoff = (uint32_t)((lane & 7) + ((lane >> 4) & 1) * 8) * FE_PITCHB
                        + (uint32_t)(wm + ((lane >> 3) & 1) * 8) * 2;
    const uint32_t boff = (uint32_t)((lane & 7) + ((lane >> 3) & 1) * 8) * RE_PITCHB
                        + (uint32_t)(((lane >> 4) & 1) * 8) * 2;

    float acc[2][8][4];
#pragma unroll
    for (int i = 0; i < 2; i++)
#pragma unroll
        for (int j = 0; j < 8; j++)
#pragma unroll
            for (int q = 0; q < 4; q++) acc[i][j][q] = 0.f;

    issue_tile(0, 0);

    for (int kt = 0; kt < O_NT; kt++) {
        const int st = kt & 1;
        if (kt + 1 < O_NT) { issue_tile(kt + 1, st ^ 1); CP_WAIT(1); }
        else               { CP_WAIT(0); }
        __syncthreads();

        const uint32_t base = smb + st * O_STAGE;
#pragma unroll
        for (int s = 0; s < 2; s++) {
            const uint32_t arow  = base + O_FEH + aoff + (uint32_t)(s * 16) * FE_PITCHB;
            const uint32_t alrow = arow + (O_FEL - O_FEH);
            const uint32_t brow  = base + O_REH + boff + (uint32_t)(s * 16) * RE_PITCHB;
            const uint32_t blrow = brow + (O_REL - O_REH);
            uint32_t ah[2][4], al[2][4];
#pragma unroll
            for (int mi = 0; mi < 2; mi++) {
                LDSM4T(ah[mi], arow + mi * 32);
                LDSM4T(al[mi], alrow + mi * 32);
            }
            uint32_t bh[4][4], bl[4][4];
#pragma unroll
            for (int n16 = 0; n16 < 4; n16++) {
                LDSM4T(bh[n16], brow + n16 * 32);
                LDSM4T(bl[n16], blrow + n16 * 32);
            }
#pragma unroll
            for (int mi = 0; mi < 2; mi++)
#pragma unroll
                for (int n16 = 0; n16 < 4; n16++)
#pragma unroll
                    for (int h = 0; h < 2; h++) {
                        float* d = acc[mi][n16 * 2 + h];
                        MMA16816(d, ah[mi], bh[n16][h * 2], bh[n16][h * 2 + 1]);
                        MMA16816(d, ah[mi], bl[n16][h * 2], bl[n16][h * 2 + 1]);
                        MMA16816(d, al[mi], bh[n16][h * 2], bh[n16][h * 2 + 1]);
                    }
        }
        __syncthreads();
    }

    const int rrow = lane >> 2, rcol = (lane & 3) * 2;
#pragma unroll
    for (int mi = 0; mi < 2; mi++)
#pragma unroll
        for (int nj = 0; nj < 8; nj++) {
            float* d = acc[mi][nj];
            int m = wm + mi * 16 + rrow;
            int n = nj * 8 + rcol;
            size_t off = (size_t)b * KFLAT + (size_t)m * RD + n;
            unsigned h, l;
            bf16_split2(d[0], d[1], h, l);
            *(unsigned*)(g_a_hi + off) = h;
            *(unsigned*)(g_a_lo + off) = l;
            bf16_split2(d[2], d[3], h, l);
            *(unsigned*)(g_a_hi + off + 8 * RD) = h;
            *(unsigned*)(g_a_lo + off + 8 * RD) = l;
        }
}

// ---------------------------------------------------------------------------
// Kernel 2: warp-mma split-K GEMM, cp.async double-buffered (R11 structure),
// KSPLIT=16 for concurrency: grid = (4, 12, 16) = 768 CTAs (~5.2/SM).
// 128 threads (4 warps, M split 4x32), warp tile 32(M) x 64(N), K-tile 32.
// ---------------------------------------------------------------------------
#define PITCHB 80
#define G_AH 0
#define G_AL 10240
#define G_BH 20480
#define G_BL 25600
#define G_STAGE 30720
#define GEMM2_DYN (2 * G_STAGE)
#define G_NT (KCHUNK / 32)   // 16

__global__ __launch_bounds__(128) void gemm2_mma()
{
    extern __shared__ char dsm[];
    const int tid  = threadIdx.x;
    const int lane = tid & 31;
    const int wid  = tid >> 5;
    const int wm   = wid * 32;

    const int mtile = blockIdx.x, ntile = blockIdx.y, ks = blockIdx.z;
    const size_t arow0 = (size_t)(mtile * 128) * KFLAT;
    const size_t brow0 = (size_t)(ntile * 64) * KFLAT;
    const int kbase = ks * KCHUNK;

    const uint32_t smb = smem_u32(dsm);
    const int row = tid >> 2, c = tid & 3;

    auto issue_tile = [&](int it, int st) {
        const int kg = kbase + it * 32;
        const uint32_t base = smb + st * G_STAGE;
#pragma unroll
        for (int u = 0; u < 4; u++) {
            int r2 = row + u * 32;
            uint32_t d = base + r2 * PITCHB + c * 16;
            size_t s = arow0 + (size_t)r2 * KFLAT + kg + c * 8;
            CP_ASYNC16(d + G_AH, g_a_hi + s);
            CP_ASYNC16(d + G_AL, g_a_lo + s);
        }
#pragma unroll
        for (int u = 0; u < 2; u++) {
            int r2 = row + u * 32;
            uint32_t d = base + r2 * PITCHB + c * 16;
            size_t s = brow0 + (size_t)r2 * KFLAT + kg + c * 8;
            CP_ASYNC16(d + G_BH, g_w_hi + s);
            CP_ASYNC16(d + G_BL, g_w_lo + s);
        }
        CP_COMMIT();
    };

    const uint32_t a_off0 = (uint32_t)(wm + (lane & 15)) * PITCHB + ((lane >> 4) << 4);
    const uint32_t b_off0 = (uint32_t)(((lane >> 4) << 3) + (lane & 7)) * PITCHB
                          + (((lane >> 3) & 1) << 4);

    float acc[2][8][4];
#pragma unroll
    for (int i = 0; i < 2; i++)
#pragma unroll
        for (int j = 0; j < 8; j++)
#pragma unroll
            for (int q = 0; q < 4; q++) acc[i][j][q] = 0.f;

    issue_tile(0, 0);

    for (int it = 0; it < G_NT; it++) {
        const int st = it & 1;
        if (it + 1 < G_NT) { issue_tile(it + 1, st ^ 1); CP_WAIT(1); }
        else               { CP_WAIT(0); }
        __syncthreads();

        const uint32_t base = smb + st * G_STAGE;
#pragma unroll
        for (int s = 0; s < 2; s++) {
            const uint32_t koff = s * 32;
            uint32_t ah[2][4], al[2][4];
#pragma unroll
            for (int i = 0; i < 2; i++) {
                uint32_t off = a_off0 + (uint32_t)(i * 16) * PITCHB + koff;
                LDSM4(ah[i], base + G_AH + off);
                LDSM4(al[i], base + G_AL + off);
            }
            uint32_t bh[4][4], bl[4][4];
#pragma unroll
            for (int j = 0; j < 4; j++) {
                uint32_t off = b_off0 + (uint32_t)(j * 16) * PITCHB + koff;
                LDSM4(bh[j], base + G_BH + off);
                LDSM4(bl[j], base + G_BL + off);
            }
#pragma unroll
            for (int i = 0; i < 2; i++)
#pragma unroll
                for (int j = 0; j < 4; j++)
#pragma unroll
                    for (int h = 0; h < 2; h++) {
                        float* d = acc[i][j * 2 + h];
                        MMA16816(d, ah[i], bh[j][h * 2], bh[j][h * 2 + 1]);
                        MMA16816(d, ah[i], bl[j][h * 2], bl[j][h * 2 + 1]);
                        MMA16816(d, al[i], bh[j][h * 2], bh[j][h * 2 + 1]);
                    }
        }
        __syncthreads();
    }

    const int rbase = mtile * 128 + wm + (lane >> 2);
    const int cbase = ntile * 64 + (lane & 3) * 2;
    float* P = g_partial + (size_t)ks * BATCH * FW;
#pragma unroll
    for (int i = 0; i < 2; i++)
#pragma unroll
        for (int nj = 0; nj < 8; nj++) {
            float* d = acc[i][nj];
            size_t r0 = (size_t)(rbase + i * 16) * FW + cbase + nj * 8;
            *(float2*)&P[r0]          = make_float2(d[0], d[1]);
            *(float2*)&P[r0 + 8 * FW] = make_float2(d[2], d[3]);
        }
}

// ---------------------------------------------------------------------------
// Kernel 3: reduce split-K partials + bias -> out[1][B][FW]
// ---------------------------------------------------------------------------
__global__ void reduce_kernel(const float* __restrict__ bias, float* __restrict__ out)
{
    int idx = blockIdx.x * 256 + threadIdx.x;
    if (idx < BATCH * FW) {
        int n = idx % FW;
        float s = bias[n];
#pragma unroll
        for (int ks = 0; ks < KSPLIT; ks++)
            s += g_partial[(size_t)ks * BATCH * FW + idx];
        out[idx] = s;
    }
}

// ---------------------------------------------------------------------------
extern "C" void kernel_launch(void* const* d_in, const int* in_sizes, int n_in,
                              void* d_out, int out_size)
{
    const void* idx_arr[2] = {nullptr, nullptr};
    int n_idx = 0;
    const float* ftab = nullptr;
    const float* rtab = nullptr;
    const float* W    = nullptr;
    const float* bias = nullptr;

    for (int i = 0; i < n_in; i++) {
        switch (in_sizes[i]) {
            case BATCH * SEQ:
                if (n_idx < 2) idx_arr[n_idx++] = d_in[i];
                break;
            case NUM_FILLERS * FD: ftab = (const float*)d_in[i]; break;
            case NUM_ROLES * RD:   rtab = (const float*)d_in[i]; break;
            case FW * KFLAT:       W    = (const float*)d_in[i]; break;
            case FW:               bias = (const float*)d_in[i]; break;
            default: break;
        }
    }

    const int* ia = (const int*)idx_arr[0];
    const int* ib = (const int*)idx_arr[1];
    float* out = (float*)d_out;

    static bool attr_done = false;
    if (!attr_done) {
        cudaFuncSetAttribute(outer_tc, cudaFuncAttributeMaxDynamicSharedMemorySize, OUTER_DYN);
        cudaFuncSetAttribute(gemm2_mma, cudaFuncAttributeMaxDynamicSharedMemorySize, GEMM2_DYN);
        attr_done = true;
    }

    detect_kernel<<<1, 1>>>(ia, ib);
    convert_all<<<W_BLK + F_BLK + R_BLK, 256>>>(W, ftab, rtab);

    outer_tc<<<BATCH, 128, OUTER_DYN>>>(ia, ib);

    dim3 grid2(BATCH / 128, FW / 64, KSPLIT);
    gemm2_mma<<<grid2, 128, GEMM2_DYN>>>();

    reduce_kernel<<<(BATCH * FW + 255) / 256, 256>>>(bias, out);
}

// round 16
// speedup vs baseline: 1.2928x; 1.2223x over previous
#include <cuda_runtime.h>
#include <cuda_fp16.h>
#include <cstdint>

// Problem constants
#define BATCH 512
#define SEQ 512
#define FD 128
#define RD 64
#define FW 768
#define KFLAT (FD*RD)   // 8192
#define KSPLIT 8
#define KCHUNK (KFLAT/KSPLIT)  // 1024
#define NUM_FILLERS 50257
#define NUM_ROLES 512

// Scratch (device globals) — fp16 split-A / rounded-B scheme
__device__ __half g_f_hi[(size_t)NUM_FILLERS * FD];
__device__ __half g_f_lo[(size_t)NUM_FILLERS * FD];
__device__ __half g_r[(size_t)NUM_ROLES * RD];        // B side of outer: single fp16
__device__ __half g_a_hi[(size_t)BATCH * KFLAT];
__device__ __half g_a_lo[(size_t)BATCH * KFLAT];
__device__ __half g_w[(size_t)FW * KFLAT];            // B side of gemm2: single fp16
__device__ float g_partial[(size_t)KSPLIT * BATCH * FW];
__device__ int   g_flags[2];

__device__ __forceinline__ uint32_t smem_u32(const void* p) {
    uint32_t a;
    asm("{ .reg .u64 t; cvta.to.shared.u64 t, %1; cvt.u32.u64 %0, t; }" : "=r"(a) : "l"(p));
    return a;
}

// ---- cp.async helpers -----------------------------------------------------
#define CP_ASYNC16(dst, src) \
    asm volatile("cp.async.cg.shared.global [%0], [%1], 16;" :: "r"(dst), "l"(src))
#define CP_COMMIT() asm volatile("cp.async.commit_group;" ::: "memory")
#define CP_WAIT(N)  asm volatile("cp.async.wait_group %0;" :: "n"(N) : "memory")

// ---- warp mma helpers -----------------------------------------------------
#define LDSM4(r, addr) \
    asm volatile("ldmatrix.sync.aligned.m8n8.x4.shared.b16 {%0,%1,%2,%3}, [%4];" \
        : "=r"((r)[0]), "=r"((r)[1]), "=r"((r)[2]), "=r"((r)[3]) : "r"(addr))

#define LDSM4T(r, addr) \
    asm volatile("ldmatrix.sync.aligned.m8n8.x4.trans.shared.b16 {%0,%1,%2,%3}, [%4];" \
        : "=r"((r)[0]), "=r"((r)[1]), "=r"((r)[2]), "=r"((r)[3]) : "r"(addr))

#define MMA16816(d, a, b0, b1) \
    asm volatile("mma.sync.aligned.m16n8k16.row.col.f32.f16.f16.f32 " \
        "{%0,%1,%2,%3}, {%4,%5,%6,%7}, {%8,%9}, {%0,%1,%2,%3};" \
        : "+f"((d)[0]), "+f"((d)[1]), "+f"((d)[2]), "+f"((d)[3]) \
        : "r"((a)[0]), "r"((a)[1]), "r"((a)[2]), "r"((a)[3]), "r"(b0), "r"(b1))

// fp16 split/round helpers
__device__ __forceinline__ void f16_split4(float4 v, uint2& h, uint2& l) {
    __half h0 = __float2half_rn(v.x), h1 = __float2half_rn(v.y);
    __half h2 = __float2half_rn(v.z), h3 = __float2half_rn(v.w);
    __half l0 = __float2half_rn(v.x - __half2float(h0));
    __half l1 = __float2half_rn(v.y - __half2float(h1));
    __half l2 = __float2half_rn(v.z - __half2float(h2));
    __half l3 = __float2half_rn(v.w - __half2float(h3));
    __half2 hp0{h0, h1}, hp1{h2, h3}, lp0{l0, l1}, lp1{l2, l3};
    h.x = *(unsigned*)&hp0; h.y = *(unsigned*)&hp1;
    l.x = *(unsigned*)&lp0; l.y = *(unsigned*)&lp1;
}
__device__ __forceinline__ void f16_round4(float4 v, uint2& h) {
    __half2 hp0{__float2half_rn(v.x), __float2half_rn(v.y)};
    __half2 hp1{__float2half_rn(v.z), __float2half_rn(v.w)};
    h.x = *(unsigned*)&hp0; h.y = *(unsigned*)&hp1;
}
__device__ __forceinline__ void f16_split2(float a, float b, unsigned& h, unsigned& l) {
    __half h0 = __float2half_rn(a), h1 = __float2half_rn(b);
    __half2 hp{h0, h1};
    __half2 lp{__float2half_rn(a - __half2float(h0)),
               __float2half_rn(b - __half2float(h1))};
    h = *(unsigned*)&hp; l = *(unsigned*)&lp;
}

// ---------------------------------------------------------------------------
// Kernel 0: input disambiguation
// ---------------------------------------------------------------------------
__global__ void detect_kernel(const int* __restrict__ a, const int* __restrict__ b)
{
    if (threadIdx.x != 0 || blockIdx.x != 0) return;
    int odd = 0;
#pragma unroll 8
    for (int i = 0; i < 256; i++) odd |= a[2 * i + 1];
    const int is64 = (odd == 0) ? 1 : 0;
    const int s = is64 ? 2 : 1;
    int amax = 0, bmax = 0;
#pragma unroll 8
    for (int i = 0; i < 256; i++) {
        amax = max(amax, a[i * s]);
        bmax = max(bmax, b[i * s]);
    }
    g_flags[0] = (amax < NUM_ROLES && bmax >= NUM_ROLES) ? 1 : 0;
    g_flags[1] = is64;
}

// ---------------------------------------------------------------------------
// One-shot converters: W -> fp16 (round), ftab -> fp16 hi/lo, rtab -> fp16
// ---------------------------------------------------------------------------
#define W4   ((size_t)FW * KFLAT / 4)
#define F4   ((size_t)NUM_FILLERS * FD / 4)
#define R4   ((size_t)NUM_ROLES * RD / 4)
#define W_BLK  6144
#define F_BLK  6283
#define R_BLK  32
__global__ __launch_bounds__(256) void convert_all(
    const float* __restrict__ W, const float* __restrict__ FT,
    const float* __restrict__ RT)
{
    const int bx = blockIdx.x;
    if (bx < W_BLK) {
        size_t i = (size_t)bx * 256 + threadIdx.x;
        if (i >= W4) return;
        uint2 h;
        f16_round4(((const float4*)W)[i], h);
        ((uint2*)g_w)[i] = h;
    } else if (bx < W_BLK + F_BLK) {
        size_t i = (size_t)(bx - W_BLK) * 256 + threadIdx.x;
        if (i >= F4) return;
        uint2 h, l;
        f16_split4(((const float4*)FT)[i], h, l);
        ((uint2*)g_f_hi)[i] = h;
        ((uint2*)g_f_lo)[i] = l;
    } else {
        size_t i = (size_t)(bx - W_BLK - F_BLK) * 256 + threadIdx.x;
        if (i >= R4) return;
        uint2 h;
        f16_round4(((const float4*)RT)[i], h);
        ((uint2*)g_r)[i] = h;
    }
}

// ---------------------------------------------------------------------------
// Kernel 1: tensorized outer products, cp.async double-buffered.
//   outer[b] = fe^T @ re : M=128 x N=64 x K=512.
//   2-pass fp16: (fe_hi + fe_lo) x fp16(re), fp32 accum.
// grid = 512, 128 threads (4 warps, M split 4x32), warp tile 32(M) x 64(N).
// ---------------------------------------------------------------------------
#define FE_PITCHB 272
#define RE_PITCHB 144
#define O_FEH 0
#define O_FEL 8704
#define O_RE  17408
#define O_STAGE 22016
#define OUTER_DYN (2 * O_STAGE)
#define O_NT (SEQ / 32)   // 16

__global__ __launch_bounds__(128) void outer_tc(
    const int* __restrict__ ia, const int* __restrict__ ib)
{
    extern __shared__ char dsm[];
    __shared__ int sf[SEQ], sr[SEQ];

    const int b    = blockIdx.x;
    const int tid  = threadIdx.x;
    const int lane = tid & 31;
    const int wid  = tid >> 5;
    const int wm   = wid * 32;

    const int swap = g_flags[0];
    const int strd = g_flags[1] ? 2 : 1;
    const int* __restrict__ fidx = swap ? ib : ia;
    const int* __restrict__ ridx = swap ? ia : ib;

    for (int i = tid; i < SEQ; i += 128) {
        size_t e = (size_t)b * SEQ + i;
        sf[i] = min(max(fidx[e * strd], 0), NUM_FILLERS - 1);
        sr[i] = min(max(ridx[e * strd], 0), NUM_ROLES - 1);
    }
    __syncthreads();

    const uint32_t smb = smem_u32(dsm);

    const int fr = tid >> 4, fc = tid & 15;
    const int rr = tid >> 3, rc = tid & 7;

    auto issue_tile = [&](int kt, int st) {
        const int k0 = kt * 32;
        const uint32_t base = smb + st * O_STAGE;
#pragma unroll
        for (int u = 0; u < 4; u++) {
            int row = fr + u * 8;
            uint32_t d = base + row * FE_PITCHB + fc * 16;
            size_t s = (size_t)sf[k0 + row] * FD + fc * 8;
            CP_ASYNC16(d + O_FEH, g_f_hi + s);
            CP_ASYNC16(d + O_FEL, g_f_lo + s);
        }
#pragma unroll
        for (int u = 0; u < 2; u++) {
            int row = rr + u * 16;
            uint32_t d = base + O_RE + row * RE_PITCHB + rc * 16;
            size_t s = (size_t)sr[k0 + row] * RD + rc * 8;
            CP_ASYNC16(d, g_r + s);
        }
        CP_COMMIT();
    };

    const uint32_t aoff = (uint32_t)((lane & 7) + ((lane >> 4) & 1) * 8) * FE_PITCHB
                        + (uint32_t)(wm + ((lane >> 3) & 1) * 8) * 2;
    const uint32_t boff = (uint32_t)((lane & 7) + ((lane >> 3) & 1) * 8) * RE_PITCHB
                        + (uint32_t)(((lane >> 4) & 1) * 8) * 2;

    float acc[2][8][4];
#pragma unroll
    for (int i = 0; i < 2; i++)
#pragma unroll
        for (int j = 0; j < 8; j++)
#pragma unroll
            for (int q = 0; q < 4; q++) acc[i][j][q] = 0.f;

    issue_tile(0, 0);

    for (int kt = 0; kt < O_NT; kt++) {
        const int st = kt & 1;
        if (kt + 1 < O_NT) { issue_tile(kt + 1, st ^ 1); CP_WAIT(1); }
        else               { CP_WAIT(0); }
        __syncthreads();

        const uint32_t base = smb + st * O_STAGE;
#pragma unroll
        for (int s = 0; s < 2; s++) {
            const uint32_t arow  = base + O_FEH + aoff + (uint32_t)(s * 16) * FE_PITCHB;
            const uint32_t alrow = arow + (O_FEL - O_FEH);
            const uint32_t brow  = base + O_RE + boff + (uint32_t)(s * 16) * RE_PITCHB;
            uint32_t ah[2][4], al[2][4];
#pragma unroll
            for (int mi = 0; mi < 2; mi++) {
                LDSM4T(ah[mi], arow + mi * 32);
                LDSM4T(al[mi], alrow + mi * 32);
            }
            uint32_t bh[4][4];
#pragma unroll
            for (int n16 = 0; n16 < 4; n16++)
                LDSM4T(bh[n16], brow + n16 * 32);
#pragma unroll
            for (int mi = 0; mi < 2; mi++)
#pragma unroll
                for (int n16 = 0; n16 < 4; n16++)
#pragma unroll
                    for (int h = 0; h < 2; h++) {
                        float* d = acc[mi][n16 * 2 + h];
                        MMA16816(d, ah[mi], bh[n16][h * 2], bh[n16][h * 2 + 1]);
                        MMA16816(d, al[mi], bh[n16][h * 2], bh[n16][h * 2 + 1]);
                    }
        }
        __syncthreads();
    }

    const int rrow = lane >> 2, rcol = (lane & 3) * 2;
#pragma unroll
    for (int mi = 0; mi < 2; mi++)
#pragma unroll
        for (int nj = 0; nj < 8; nj++) {
            float* d = acc[mi][nj];
            int m = wm + mi * 16 + rrow;
            int n = nj * 8 + rcol;
            size_t off = (size_t)b * KFLAT + (size_t)m * RD + n;
            unsigned h, l;
            f16_split2(d[0], d[1], h, l);
            *(unsigned*)(g_a_hi + off) = h;
            *(unsigned*)(g_a_lo + off) = l;
            f16_split2(d[2], d[3], h, l);
            *(unsigned*)(g_a_hi + off + 8 * RD) = h;
            *(unsigned*)(g_a_lo + off + 8 * RD) = l;
        }
}

// ---------------------------------------------------------------------------
// Kernel 2: warp-mma split-K GEMM, cp.async double-buffered.
//   2-pass fp16: (a_hi + a_lo) x fp16(W), fp32 accum.
// grid = (4, 12, 8), 128 threads (4 warps), warp tile 32(M) x 64(N),
// CTA 128x64, K-tile 32.
// ---------------------------------------------------------------------------
#define PITCHB 80
#define G_AH 0
#define G_AL 10240
#define G_B  20480
#define G_STAGE 25600
#define GEMM2_DYN (2 * G_STAGE)
#define G_NT (KCHUNK / 32)   // 32

__global__ __launch_bounds__(128) void gemm2_mma()
{
    extern __shared__ char dsm[];
    const int tid  = threadIdx.x;
    const int lane = tid & 31;
    const int wid  = tid >> 5;
    const int wm   = wid * 32;

    const int mtile = blockIdx.x, ntile = blockIdx.y, ks = blockIdx.z;
    const size_t arow0 = (size_t)(mtile * 128) * KFLAT;
    const size_t brow0 = (size_t)(ntile * 64) * KFLAT;
    const int kbase = ks * KCHUNK;

    const uint32_t smb = smem_u32(dsm);
    const int row = tid >> 2, c = tid & 3;

    auto issue_tile = [&](int it, int st) {
        const int kg = kbase + it * 32;
        const uint32_t base = smb + st * G_STAGE;
#pragma unroll
        for (int u = 0; u < 4; u++) {
            int r2 = row + u * 32;
            uint32_t d = base + r2 * PITCHB + c * 16;
            size_t s = arow0 + (size_t)r2 * KFLAT + kg + c * 8;
            CP_ASYNC16(d + G_AH, g_a_hi + s);
            CP_ASYNC16(d + G_AL, g_a_lo + s);
        }
#pragma unroll
        for (int u = 0; u < 2; u++) {
            int r2 = row + u * 32;
            uint32_t d = base + G_B + r2 * PITCHB + c * 16;
            size_t s = brow0 + (size_t)r2 * KFLAT + kg + c * 8;
            CP_ASYNC16(d, g_w + s);
        }
        CP_COMMIT();
    };

    const uint32_t a_off0 = (uint32_t)(wm + (lane & 15)) * PITCHB + ((lane >> 4) << 4);
    const uint32_t b_off0 = (uint32_t)(((lane >> 4) << 3) + (lane & 7)) * PITCHB
                          + (((lane >> 3) & 1) << 4);

    float acc[2][8][4];
#pragma unroll
    for (int i = 0; i < 2; i++)
#pragma unroll
        for (int j = 0; j < 8; j++)
#pragma unroll
            for (int q = 0; q < 4; q++) acc[i][j][q] = 0.f;

    issue_tile(0, 0);

    for (int it = 0; it < G_NT; it++) {
        const int st = it & 1;
        if (it + 1 < G_NT) { issue_tile(it + 1, st ^ 1); CP_WAIT(1); }
        else               { CP_WAIT(0); }
        __syncthreads();

        const uint32_t base = smb + st * G_STAGE;
#pragma unroll
        for (int s = 0; s < 2; s++) {
            const uint32_t koff = s * 32;
            uint32_t ah[2][4], al[2][4];
#pragma unroll
            for (int i = 0; i < 2; i++) {
                uint32_t off = a_off0 + (uint32_t)(i * 16) * PITCHB + koff;
                LDSM4(ah[i], base + G_AH + off);
                LDSM4(al[i], base + G_AL + off);
            }
            uint32_t bh[4][4];
#pragma unroll
            for (int j = 0; j < 4; j++) {
                uint32_t off = b_off0 + (uint32_t)(j * 16) * PITCHB + koff;
                LDSM4(bh[j], base + G_B + off);
            }
#pragma unroll
            for (int i = 0; i < 2; i++)
#pragma unroll
                for (int j = 0; j < 4; j++)
#pragma unroll
                    for (int h = 0; h < 2; h++) {
                        float* d = acc[i][j * 2 + h];
                        MMA16816(d, ah[i], bh[j][h * 2], bh[j][h * 2 + 1]);
                        MMA16816(d, al[i], bh[j][h * 2], bh[j][h * 2 + 1]);
                    }
        }
        __syncthreads();
    }

    const int rbase = mtile * 128 + wm + (lane >> 2);
    const int cbase = ntile * 64 + (lane & 3) * 2;
    float* P = g_partial + (size_t)ks * BATCH * FW;
#pragma unroll
    for (int i = 0; i < 2; i++)
#pragma unroll
        for (int nj = 0; nj < 8; nj++) {
            float* d = acc[i][nj];
            size_t r0 = (size_t)(rbase + i * 16) * FW + cbase + nj * 8;
            *(float2*)&P[r0]          = make_float2(d[0], d[1]);
            *(float2*)&P[r0 + 8 * FW] = make_float2(d[2], d[3]);
        }
}

// ---------------------------------------------------------------------------
// Kernel 3: reduce split-K partials + bias -> out[1][B][FW]
// ---------------------------------------------------------------------------
__global__ void reduce_kernel(const float* __restrict__ bias, float* __restrict__ out)
{
    int idx = blockIdx.x * 256 + threadIdx.x;
    if (idx < BATCH * FW) {
        int n = idx % FW;
        float s = bias[n];
#pragma unroll
        for (int ks = 0; ks < KSPLIT; ks++)
            s += g_partial[(size_t)ks * BATCH * FW + idx];
        out[idx] = s;
    }
}

// ---------------------------------------------------------------------------
extern "C" void kernel_launch(void* const* d_in, const int* in_sizes, int n_in,
                              void* d_out, int out_size)
{
    const void* idx_arr[2] = {nullptr, nullptr};
    int n_idx = 0;
    const float* ftab = nullptr;
    const float* rtab = nullptr;
    const float* W    = nullptr;
    const float* bias = nullptr;

    for (int i = 0; i < n_in; i++) {
        switch (in_sizes[i]) {
            case BATCH * SEQ:
                if (n_idx < 2) idx_arr[n_idx++] = d_in[i];
                break;
            case NUM_FILLERS * FD: ftab = (const float*)d_in[i]; break;
            case NUM_ROLES * RD:   rtab = (const float*)d_in[i]; break;
            case FW * KFLAT:       W    = (const float*)d_in[i]; break;
            case FW:               bias = (const float*)d_in[i]; break;
            default: break;
        }
    }

    const int* ia = (const int*)idx_arr[0];
    const int* ib = (const int*)idx_arr[1];
    float* out = (float*)d_out;

    static bool attr_done = false;
    if (!attr_done) {
        cudaFuncSetAttribute(outer_tc, cudaFuncAttributeMaxDynamicSharedMemorySize, OUTER_DYN);
        cudaFuncSetAttribute(gemm2_mma, cudaFuncAttributeMaxDynamicSharedMemorySize, GEMM2_DYN);
        attr_done = true;
    }

    detect_kernel<<<1, 1>>>(ia, ib);
    convert_all<<<W_BLK + F_BLK + R_BLK, 256>>>(W, ftab, rtab);

    outer_tc<<<BATCH, 128, OUTER_DYN>>>(ia, ib);

    dim3 grid2(BATCH / 128, FW / 64, KSPLIT);
    gemm2_mma<<<grid2, 128, GEMM2_DYN>>>();

    reduce_kernel<<<(BATCH * FW + 255) / 256, 256>>>(bias, out);
}

// round 17
// speedup vs baseline: 1.3329x; 1.0310x over previous
#include <cuda_runtime.h>
#include <cuda_fp16.h>
#include <cstdint>

// Problem constants
#define BATCH 512
#define SEQ 512
#define FD 128
#define RD 64
#define FW 768
#define KFLAT (FD*RD)   // 8192
#define KSPLIT 16
#define KCHUNK (KFLAT/KSPLIT)  // 512
#define NUM_FILLERS 50257
#define NUM_ROLES 512

// Scratch (device globals) — fp16 split-A / rounded-B scheme
__device__ __half g_f_hi[(size_t)NUM_FILLERS * FD];
__device__ __half g_f_lo[(size_t)NUM_FILLERS * FD];
__device__ __half g_r[(size_t)NUM_ROLES * RD];
__device__ __half g_a_hi[(size_t)BATCH * KFLAT];
__device__ __half g_a_lo[(size_t)BATCH * KFLAT];
__device__ __half g_w[(size_t)FW * KFLAT];
__device__ float g_partial[(size_t)KSPLIT * BATCH * FW];   // 25.2 MB
__device__ int   g_flags[2];

__device__ __forceinline__ uint32_t smem_u32(const void* p) {
    uint32_t a;
    asm("{ .reg .u64 t; cvta.to.shared.u64 t, %1; cvt.u32.u64 %0, t; }" : "=r"(a) : "l"(p));
    return a;
}

// ---- cp.async helpers -----------------------------------------------------
#define CP_ASYNC16(dst, src) \
    asm volatile("cp.async.cg.shared.global [%0], [%1], 16;" :: "r"(dst), "l"(src))
#define CP_COMMIT() asm volatile("cp.async.commit_group;" ::: "memory")
#define CP_WAIT(N)  asm volatile("cp.async.wait_group %0;" :: "n"(N) : "memory")

// ---- warp mma helpers -----------------------------------------------------
#define LDSM4(r, addr) \
    asm volatile("ldmatrix.sync.aligned.m8n8.x4.shared.b16 {%0,%1,%2,%3}, [%4];" \
        : "=r"((r)[0]), "=r"((r)[1]), "=r"((r)[2]), "=r"((r)[3]) : "r"(addr))

#define LDSM4T(r, addr) \
    asm volatile("ldmatrix.sync.aligned.m8n8.x4.trans.shared.b16 {%0,%1,%2,%3}, [%4];" \
        : "=r"((r)[0]), "=r"((r)[1]), "=r"((r)[2]), "=r"((r)[3]) : "r"(addr))

#define MMA16816(d, a, b0, b1) \
    asm volatile("mma.sync.aligned.m16n8k16.row.col.f32.f16.f16.f32 " \
        "{%0,%1,%2,%3}, {%4,%5,%6,%7}, {%8,%9}, {%0,%1,%2,%3};" \
        : "+f"((d)[0]), "+f"((d)[1]), "+f"((d)[2]), "+f"((d)[3]) \
        : "r"((a)[0]), "r"((a)[1]), "r"((a)[2]), "r"((a)[3]), "r"(b0), "r"(b1))

// fp16 split/round helpers
__device__ __forceinline__ void f16_split4(float4 v, uint2& h, uint2& l) {
    __half h0 = __float2half_rn(v.x), h1 = __float2half_rn(v.y);
    __half h2 = __float2half_rn(v.z), h3 = __float2half_rn(v.w);
    __half l0 = __float2half_rn(v.x - __half2float(h0));
    __half l1 = __float2half_rn(v.y - __half2float(h1));
    __half l2 = __float2half_rn(v.z - __half2float(h2));
    __half l3 = __float2half_rn(v.w - __half2float(h3));
    __half2 hp0{h0, h1}, hp1{h2, h3}, lp0{l0, l1}, lp1{l2, l3};
    h.x = *(unsigned*)&hp0; h.y = *(unsigned*)&hp1;
    l.x = *(unsigned*)&lp0; l.y = *(unsigned*)&lp1;
}
__device__ __forceinline__ void f16_round4(float4 v, uint2& h) {
    __half2 hp0{__float2half_rn(v.x), __float2half_rn(v.y)};
    __half2 hp1{__float2half_rn(v.z), __float2half_rn(v.w)};
    h.x = *(unsigned*)&hp0; h.y = *(unsigned*)&hp1;
}
__device__ __forceinline__ void f16_split2(float a, float b, unsigned& h, unsigned& l) {
    __half h0 = __float2half_rn(a), h1 = __float2half_rn(b);
    __half2 hp{h0, h1};
    __half2 lp{__float2half_rn(a - __half2float(h0)),
               __float2half_rn(b - __half2float(h1))};
    h = *(unsigned*)&hp; l = *(unsigned*)&lp;
}

// ---------------------------------------------------------------------------
// Kernel 0: input disambiguation
// ---------------------------------------------------------------------------
__global__ void detect_kernel(const int* __restrict__ a, const int* __restrict__ b)
{
    if (threadIdx.x != 0 || blockIdx.x != 0) return;
    int odd = 0;
#pragma unroll 8
    for (int i = 0; i < 256; i++) odd |= a[2 * i + 1];
    const int is64 = (odd == 0) ? 1 : 0;
    const int s = is64 ? 2 : 1;
    int amax = 0, bmax = 0;
#pragma unroll 8
    for (int i = 0; i < 256; i++) {
        amax = max(amax, a[i * s]);
        bmax = max(bmax, b[i * s]);
    }
    g_flags[0] = (amax < NUM_ROLES && bmax >= NUM_ROLES) ? 1 : 0;
    g_flags[1] = is64;
}

// ---------------------------------------------------------------------------
// One-shot converters: W -> fp16 (round), ftab -> fp16 hi/lo, rtab -> fp16
// ---------------------------------------------------------------------------
#define W4   ((size_t)FW * KFLAT / 4)
#define F4   ((size_t)NUM_FILLERS * FD / 4)
#define R4   ((size_t)NUM_ROLES * RD / 4)
#define W_BLK  6144
#define F_BLK  6283
#define R_BLK  32
__global__ __launch_bounds__(256) void convert_all(
    const float* __restrict__ W, const float* __restrict__ FT,
    const float* __restrict__ RT)
{
    const int bx = blockIdx.x;
    if (bx < W_BLK) {
        size_t i = (size_t)bx * 256 + threadIdx.x;
        if (i >= W4) return;
        uint2 h;
        f16_round4(((const float4*)W)[i], h);
        ((uint2*)g_w)[i] = h;
    } else if (bx < W_BLK + F_BLK) {
        size_t i = (size_t)(bx - W_BLK) * 256 + threadIdx.x;
        if (i >= F4) return;
        uint2 h, l;
        f16_split4(((const float4*)FT)[i], h, l);
        ((uint2*)g_f_hi)[i] = h;
        ((uint2*)g_f_lo)[i] = l;
    } else {
        size_t i = (size_t)(bx - W_BLK - F_BLK) * 256 + threadIdx.x;
        if (i >= R4) return;
        uint2 h;
        f16_round4(((const float4*)RT)[i], h);
        ((uint2*)g_r)[i] = h;
    }
}

// ---------------------------------------------------------------------------
// Kernel 1: tensorized outer products, cp.async double-buffered (unchanged).
//   outer[b] = fe^T @ re : M=128 x N=64 x K=512. 2-pass fp16, fp32 accum.
// grid = 512, 128 threads (4 warps, M split 4x32), warp tile 32(M) x 64(N).
// ---------------------------------------------------------------------------
#define FE_PITCHB 272
#define RE_PITCHB 144
#define O_FEH 0
#define O_FEL 8704
#define O_RE  17408
#define O_STAGE 22016
#define OUTER_DYN (2 * O_STAGE)
#define O_NT (SEQ / 32)   // 16

__global__ __launch_bounds__(128) void outer_tc(
    const int* __restrict__ ia, const int* __restrict__ ib)
{
    extern __shared__ char dsm[];
    __shared__ int sf[SEQ], sr[SEQ];

    const int b    = blockIdx.x;
    const int tid  = threadIdx.x;
    const int lane = tid & 31;
    const int wid  = tid >> 5;
    const int wm   = wid * 32;

    const int swap = g_flags[0];
    const int strd = g_flags[1] ? 2 : 1;
    const int* __restrict__ fidx = swap ? ib : ia;
    const int* __restrict__ ridx = swap ? ia : ib;

    for (int i = tid; i < SEQ; i += 128) {
        size_t e = (size_t)b * SEQ + i;
        sf[i] = min(max(fidx[e * strd], 0), NUM_FILLERS - 1);
        sr[i] = min(max(ridx[e * strd], 0), NUM_ROLES - 1);
    }
    __syncthreads();

    const uint32_t smb = smem_u32(dsm);

    const int fr = tid >> 4, fc = tid & 15;
    const int rr = tid >> 3, rc = tid & 7;

    auto issue_tile = [&](int kt, int st) {
        const int k0 = kt * 32;
        const uint32_t base = smb + st * O_STAGE;
#pragma unroll
        for (int u = 0; u < 4; u++) {
            int row = fr + u * 8;
            uint32_t d = base + row * FE_PITCHB + fc * 16;
            size_t s = (size_t)sf[k0 + row] * FD + fc * 8;
            CP_ASYNC16(d + O_FEH, g_f_hi + s);
            CP_ASYNC16(d + O_FEL, g_f_lo + s);
        }
#pragma unroll
        for (int u = 0; u < 2; u++) {
            int row = rr + u * 16;
            uint32_t d = base + O_RE + row * RE_PITCHB + rc * 16;
            size_t s = (size_t)sr[k0 + row] * RD + rc * 8;
            CP_ASYNC16(d, g_r + s);
        }
        CP_COMMIT();
    };

    const uint32_t aoff = (uint32_t)((lane & 7) + ((lane >> 4) & 1) * 8) * FE_PITCHB
                        + (uint32_t)(wm + ((lane >> 3) & 1) * 8) * 2;
    const uint32_t boff = (uint32_t)((lane & 7) + ((lane >> 3) & 1) * 8) * RE_PITCHB
                        + (uint32_t)(((lane >> 4) & 1) * 8) * 2;

    float acc[2][8][4];
#pragma unroll
    for (int i = 0; i < 2; i++)
#pragma unroll
        for (int j = 0; j < 8; j++)
#pragma unroll
            for (int q = 0; q < 4; q++) acc[i][j][q] = 0.f;

    issue_tile(0, 0);

    for (int kt = 0; kt < O_NT; kt++) {
        const int st = kt & 1;
        if (kt + 1 < O_NT) { issue_tile(kt + 1, st ^ 1); CP_WAIT(1); }
        else               { CP_WAIT(0); }
        __syncthreads();

        const uint32_t base = smb + st * O_STAGE;
#pragma unroll
        for (int s = 0; s < 2; s++) {
            const uint32_t arow  = base + O_FEH + aoff + (uint32_t)(s * 16) * FE_PITCHB;
            const uint32_t alrow = arow + (O_FEL - O_FEH);
            const uint32_t brow  = base + O_RE + boff + (uint32_t)(s * 16) * RE_PITCHB;
            uint32_t ah[2][4], al[2][4];
#pragma unroll
            for (int mi = 0; mi < 2; mi++) {
                LDSM4T(ah[mi], arow + mi * 32);
                LDSM4T(al[mi], alrow + mi * 32);
            }
            uint32_t bh[4][4];
#pragma unroll
            for (int n16 = 0; n16 < 4; n16++)
                LDSM4T(bh[n16], brow + n16 * 32);
#pragma unroll
            for (int mi = 0; mi < 2; mi++)
#pragma unroll
                for (int n16 = 0; n16 < 4; n16++)
#pragma unroll
                    for (int h = 0; h < 2; h++) {
                        float* d = acc[mi][n16 * 2 + h];
                        MMA16816(d, ah[mi], bh[n16][h * 2], bh[n16][h * 2 + 1]);
                        MMA16816(d, al[mi], bh[n16][h * 2], bh[n16][h * 2 + 1]);
                    }
        }
        __syncthreads();
    }

    const int rrow = lane >> 2, rcol = (lane & 3) * 2;
#pragma unroll
    for (int mi = 0; mi < 2; mi++)
#pragma unroll
        for (int nj = 0; nj < 8; nj++) {
            float* d = acc[mi][nj];
            int m = wm + mi * 16 + rrow;
            int n = nj * 8 + rcol;
            size_t off = (size_t)b * KFLAT + (size_t)m * RD + n;
            unsigned h, l;
            f16_split2(d[0], d[1], h, l);
            *(unsigned*)(g_a_hi + off) = h;
            *(unsigned*)(g_a_lo + off) = l;
            f16_split2(d[2], d[3], h, l);
            *(unsigned*)(g_a_hi + off + 8 * RD) = h;
            *(unsigned*)(g_a_lo + off + 8 * RD) = l;
        }
}

// ---------------------------------------------------------------------------
// Kernel 2: warp-mma split-K GEMM, cp.async double-buffered.
//   2-pass fp16: (a_hi + a_lo) x fp16(W), fp32 accum.
// CTA tile 128(M) x 128(N), 256 threads (8 warps: 4M x 2N), warp 32x64.
// grid = (4, 6, 16) = 384 CTAs. K-tile 32. Stage 30.7 KB x2 = 61.4 KB.
// ---------------------------------------------------------------------------
#define PITCHB 80
#define G_AH 0
#define G_AL 10240
#define G_B  20480
#define G_STAGE 30720
#define GEMM2_DYN (2 * G_STAGE)
#define G_NT (KCHUNK / 32)   // 16

__global__ __launch_bounds__(256) void gemm2_mma()
{
    extern __shared__ char dsm[];
    const int tid  = threadIdx.x;
    const int lane = tid & 31;
    const int wid  = tid >> 5;          // 0..7
    const int wm   = (wid & 3) * 32;    // M offset
    const int wn   = (wid >> 2) * 64;   // N offset (0 or 64)

    const int mtile = blockIdx.x, ntile = blockIdx.y, ks = blockIdx.z;
    const size_t arow0 = (size_t)(mtile * 128) * KFLAT;
    const size_t brow0 = (size_t)(ntile * 128) * KFLAT;
    const int kbase = ks * KCHUNK;

    const uint32_t smb = smem_u32(dsm);
    const int row = tid >> 2, c = tid & 3;   // row 0..63, chunk 0..3

    auto issue_tile = [&](int it, int st) {
        const int kg = kbase + it * 32;
        const uint32_t base = smb + st * G_STAGE;
#pragma unroll
        for (int u = 0; u < 2; u++) {
            int r2 = row + u * 64;           // A rows 0..127
            uint32_t d = base + r2 * PITCHB + c * 16;
            size_t s = arow0 + (size_t)r2 * KFLAT + kg + c * 8;
            CP_ASYNC16(d + G_AH, g_a_hi + s);
            CP_ASYNC16(d + G_AL, g_a_lo + s);
        }
#pragma unroll
        for (int u = 0; u < 2; u++) {
            int r2 = row + u * 64;           // B rows 0..127
            uint32_t d = base + G_B + r2 * PITCHB + c * 16;
            size_t s = brow0 + (size_t)r2 * KFLAT + kg + c * 8;
            CP_ASYNC16(d, g_w + s);
        }
        CP_COMMIT();
    };

    const uint32_t a_off0 = (uint32_t)(wm + (lane & 15)) * PITCHB + ((lane >> 4) << 4);
    const uint32_t b_off0 = (uint32_t)(wn + ((lane >> 4) << 3) + (lane & 7)) * PITCHB
                          + (((lane >> 3) & 1) << 4);

    float acc[2][8][4];
#pragma unroll
    for (int i = 0; i < 2; i++)
#pragma unroll
        for (int j = 0; j < 8; j++)
#pragma unroll
            for (int q = 0; q < 4; q++) acc[i][j][q] = 0.f;

    issue_tile(0, 0);

    for (int it = 0; it < G_NT; it++) {
        const int st = it & 1;
        if (it + 1 < G_NT) { issue_tile(it + 1, st ^ 1); CP_WAIT(1); }
        else               { CP_WAIT(0); }
        __syncthreads();

        const uint32_t base = smb + st * G_STAGE;
#pragma unroll
        for (int s = 0; s < 2; s++) {
            const uint32_t koff = s * 32;
            uint32_t ah[2][4], al[2][4];
#pragma unroll
            for (int i = 0; i < 2; i++) {
                uint32_t off = a_off0 + (uint32_t)(i * 16) * PITCHB + koff;
                LDSM4(ah[i], base + G_AH + off);
                LDSM4(al[i], base + G_AL + off);
            }
            uint32_t bh[4][4];
#pragma unroll
            for (int j = 0; j < 4; j++) {
                uint32_t off = b_off0 + (uint32_t)(j * 16) * PITCHB + koff;
                LDSM4(bh[j], base + G_B + off);
            }
#pragma unroll
            for (int i = 0; i < 2; i++)
#pragma unroll
                for (int j = 0; j < 4; j++)
#pragma unroll
                    for (int h = 0; h < 2; h++) {
                        float* d = acc[i][j * 2 + h];
                        MMA16816(d, ah[i], bh[j][h * 2], bh[j][h * 2 + 1]);
                        MMA16816(d, al[i], bh[j][h * 2], bh[j][h * 2 + 1]);
                    }
        }
        __syncthreads();
    }

    const int rbase = mtile * 128 + wm + (lane >> 2);
    const int cbase = ntile * 128 + wn + (lane & 3) * 2;
    float* P = g_partial + (size_t)ks * BATCH * FW;
#pragma unroll
    for (int i = 0; i < 2; i++)
#pragma unroll
        for (int nj = 0; nj < 8; nj++) {
            float* d = acc[i][nj];
            size_t r0 = (size_t)(rbase + i * 16) * FW + cbase + nj * 8;
            *(float2*)&P[r0]          = make_float2(d[0], d[1]);
            *(float2*)&P[r0 + 8 * FW] = make_float2(d[2], d[3]);
        }
}

// ---------------------------------------------------------------------------
// Kernel 3: reduce split-K partials + bias -> out[1][B][FW] (float4)
// 512*768/4 = 98304 float4; 384 blocks x 256 threads, 1 float4 each.
// ---------------------------------------------------------------------------
__global__ __launch_bounds__(256) void reduce_kernel(
    const float* __restrict__ bias, float* __restrict__ out)
{
    int i4 = blockIdx.x * 256 + threadIdx.x;
    if (i4 >= BATCH * FW / 4) return;
    const float4* bias4 = (const float4*)bias;
    float4 s = bias4[i4 % (FW / 4)];
#pragma unroll
    for (int ks = 0; ks < KSPLIT; ks++) {
        float4 p = ((const float4*)(g_partial + (size_t)ks * BATCH * FW))[i4];
        s.x += p.x; s.y += p.y; s.z += p.z; s.w += p.w;
    }
    ((float4*)out)[i4] = s;
}

// ---------------------------------------------------------------------------
extern "C" void kernel_launch(void* const* d_in, const int* in_sizes, int n_in,
                              void* d_out, int out_size)
{
    const void* idx_arr[2] = {nullptr, nullptr};
    int n_idx = 0;
    const float* ftab = nullptr;
    const float* rtab = nullptr;
    const float* W    = nullptr;
    const float* bias = nullptr;

    for (int i = 0; i < n_in; i++) {
        switch (in_sizes[i]) {
            case BATCH * SEQ:
                if (n_idx < 2) idx_arr[n_idx++] = d_in[i];
                break;
            case NUM_FILLERS * FD: ftab = (const float*)d_in[i]; break;
            case NUM_ROLES * RD:   rtab = (const float*)d_in[i]; break;
            case FW * KFLAT:       W    = (const float*)d_in[i]; break;
            case FW:               bias = (const float*)d_in[i]; break;
            default: break;
        }
    }

    const int* ia = (const int*)idx_arr[0];
    const int* ib = (const int*)idx_arr[1];
    float* out = (float*)d_out;

    static bool attr_done = false;
    if (!attr_done) {
        cudaFuncSetAttribute(outer_tc, cudaFuncAttributeMaxDynamicSharedMemorySize, OUTER_DYN);
        cudaFuncSetAttribute(gemm2_mma, cudaFuncAttributeMaxDynamicSharedMemorySize, GEMM2_DYN);
        attr_done = true;
    }

    detect_kernel<<<1, 1>>>(ia, ib);
    convert_all<<<W_BLK + F_BLK + R_BLK, 256>>>(W, ftab, rtab);

    outer_tc<<<BATCH, 128, OUTER_DYN>>>(ia, ib);

    dim3 grid2(BATCH / 128, FW / 128, KSPLIT);
    gemm2_mma<<<grid2, 256, GEMM2_DYN>>>();

    reduce_kernel<<<(BATCH * FW / 4 + 255) / 256, 256>>>(bias, out);
}